// round 13
// baseline (speedup 1.0000x reference)
#include <cuda_runtime.h>
#include <math.h>

// Problem constants (fixed by setup_inputs)
#define PB   8
#define PW   1024
#define PD   1024
#define PR   64
#define PBW  (PB * PW)            // 8192

// ---------------------------------------------------------------------------
// Scratch (__device__ globals; no allocations anywhere)
// ---------------------------------------------------------------------------
__device__ float g_hnorm[(size_t)PBW * PD];        // 32 MB  rmsnorm1 out, reused for rmsnorm2 out
__device__ float g_attn [(size_t)PBW * PD];        // 32 MB  attention mix output
__device__ float g_M    [(size_t)PB * PW * PW];    // 32 MB  per-batch mixing matrix (causal)
__device__ float g_qkraw[(size_t)PBW * 2 * PR];    //  4 MB  raw qk projection
__device__ float g_qt   [(size_t)PBW * PR];        //  2 MB  q * gamma^i          [B*W, R]
__device__ float g_ktT  [(size_t)PB * PR * PW];    //  2 MB  (k * gamma^-j)^T     [B, R, W]
__device__ float g_uv   [(size_t)PD * 2 * PR];     // .5 MB  concat(u, v)
__device__ float g_gp   [(size_t)PW * PR];         //        gamma^i table
__device__ float g_gn   [(size_t)PW * PR];         //        gamma^-i table
__device__ float g_gelu [(size_t)PBW * 2 * PD];    // 64 MB  MLP hidden

// ---------------------------------------------------------------------------
// Tiled SGEMM: C[M,N] = A[M,K] @ B, 128x128 block, 8x8 per-thread microtile.
// BT=false: B is [K,N] row-major.  BT=true: B is weight [N,K] row-major (B^T).
// EPI: 0 plain store | 1 causal mask + gate*kb + alpha*acc | 3 +bias+residual
//      4 +bias then exact GELU | 5 +=bias+acc into C
// tri: 1 -> truncate K loop at (by+1)*128 (A block-lower-triangular)
//      2 -> skip blocks strictly above the diagonal (scores)
// ---------------------------------------------------------------------------
template<int EPI, bool BT>
__global__ __launch_bounds__(256, 2)
void sgemm(const float* __restrict__ A, const float* __restrict__ B,
           float* __restrict__ C, int M, int N, int K,
           long long sA, long long sB, long long sC,
           const float* __restrict__ bias, const float* __restrict__ extra,
           const float* __restrict__ g0, const float* __restrict__ g1,
           int tri)
{
    const int bx = blockIdx.x, by = blockIdx.y, bz = blockIdx.z;
    if (tri == 2 && bx > by) return;

    A += (long long)bz * sA;
    B += (long long)bz * sB;
    C += (long long)bz * sC;

    const int tid     = threadIdx.x;
    const int rowBase = by * 128;
    const int colBase = bx * 128;

    __shared__ float As[8][132];
    __shared__ float Bs[8][132];

    int Keff = K;
    if (tri == 1) { int kl = (by + 1) * 128; if (kl < Keff) Keff = kl; }

    // A tile loader: 128 rows x 8 cols, 2 threads/row (float4 each)
    const int ar  = tid >> 1;
    const int ac4 = (tid & 1) * 4;
    const long long aoff = (long long)(rowBase + ar) * K + ac4;

    // B tile loader
    int br, bc4;
    long long boff;
    if (BT) { br = tid >> 1; bc4 = (tid & 1) * 4;
              boff = (long long)(colBase + br) * K + bc4; }
    else    { br = tid >> 5; bc4 = (tid & 31) * 4;
              boff = (long long)br * N + colBase + bc4; }

    const int mBase = (tid >> 4) * 8;
    const int nBase = (tid & 15) * 8;

    float acc[8][8];
#pragma unroll
    for (int i = 0; i < 8; i++)
#pragma unroll
        for (int j = 0; j < 8; j++) acc[i][j] = 0.f;

    float4 aReg = *(const float4*)(A + aoff);
    float4 bReg = *(const float4*)(B + boff);

    for (int k0 = 0; k0 < Keff; k0 += 8) {
        __syncthreads();
        As[ac4 + 0][ar] = aReg.x; As[ac4 + 1][ar] = aReg.y;
        As[ac4 + 2][ar] = aReg.z; As[ac4 + 3][ar] = aReg.w;
        if (BT) {
            Bs[bc4 + 0][br] = bReg.x; Bs[bc4 + 1][br] = bReg.y;
            Bs[bc4 + 2][br] = bReg.z; Bs[bc4 + 3][br] = bReg.w;
        } else {
            *(float4*)&Bs[br][bc4] = bReg;
        }
        __syncthreads();

        if (k0 + 8 < Keff) {                       // register prefetch
            aReg = *(const float4*)(A + aoff + (k0 + 8));
            if (BT) bReg = *(const float4*)(B + boff + (k0 + 8));
            else    bReg = *(const float4*)(B + boff + (long long)(k0 + 8) * N);
        }

#pragma unroll
        for (int kk = 0; kk < 8; kk++) {
            float a[8], b[8];
            *(float4*)&a[0] = *(const float4*)&As[kk][mBase];
            *(float4*)&a[4] = *(const float4*)&As[kk][mBase + 4];
            *(float4*)&b[0] = *(const float4*)&Bs[kk][nBase];
            *(float4*)&b[4] = *(const float4*)&Bs[kk][nBase + 4];
#pragma unroll
            for (int i = 0; i < 8; i++)
#pragma unroll
                for (int j = 0; j < 8; j++)
                    acc[i][j] = fmaf(a[i], b[j], acc[i][j]);
        }
    }

    float gate = 0.f, alpha = 0.f;
    if (EPI == 1) {
        gate  = 1.f / (1.f + expf(-g0[0]));
        alpha = 1.f / (1.f + expf(-g1[0]));
    }

#pragma unroll
    for (int i = 0; i < 8; i++) {
        const int m = rowBase + mBase + i;
        const long long crow = (long long)m * N + colBase + nBase;
        if (EPI == 0) {
            *(float4*)&C[crow]     = make_float4(acc[i][0], acc[i][1], acc[i][2], acc[i][3]);
            *(float4*)&C[crow + 4] = make_float4(acc[i][4], acc[i][5], acc[i][6], acc[i][7]);
        } else if (EPI == 1) {
#pragma unroll
            for (int j = 0; j < 8; j++) {
                const int jj = colBase + nBase + j;
                float vv = 0.f;
                if (jj <= m)
                    vv = gate * extra[(long long)m * N + jj] + alpha * acc[i][j];
                C[crow + j] = vv;
            }
        } else if (EPI == 3) {
#pragma unroll
            for (int j = 0; j < 8; j++)
                C[crow + j] = acc[i][j] + bias[colBase + nBase + j] + extra[crow + j];
        } else if (EPI == 4) {
#pragma unroll
            for (int j = 0; j < 8; j++) {
                const float x = acc[i][j] + bias[colBase + nBase + j];
                C[crow + j] = 0.5f * x * (1.f + erff(x * 0.70710678118654752f));
            }
        } else if (EPI == 5) {
#pragma unroll
            for (int j = 0; j < 8; j++)
                C[crow + j] += acc[i][j] + bias[colBase + nBase + j];
        }
    }
}

// ---------------------------------------------------------------------------
// RMSNorm: one block per row, D = 1024, 256 threads (one float4 each)
// ---------------------------------------------------------------------------
__global__ void rmsnorm_kernel(const float* __restrict__ x, const float* __restrict__ scale,
                               float* __restrict__ y)
{
    const long long row = blockIdx.x;
    const int t = threadIdx.x;
    const float4 v  = ((const float4*)(x + row * PD))[t];
    float s = v.x * v.x + v.y * v.y + v.z * v.z + v.w * v.w;
#pragma unroll
    for (int o = 16; o; o >>= 1) s += __shfl_xor_sync(0xffffffffu, s, o);
    __shared__ float ws[8];
    if ((t & 31) == 0) ws[t >> 5] = s;
    __syncthreads();
    const float tot = ws[0] + ws[1] + ws[2] + ws[3] + ws[4] + ws[5] + ws[6] + ws[7];
    const float r = rsqrtf(tot * (1.f / PD) + 1e-8f);
    const float4 sc = ((const float4*)scale)[t];
    ((float4*)(y + row * PD))[t] =
        make_float4(v.x * r * sc.x, v.y * r * sc.y, v.z * r * sc.z, v.w * r * sc.w);
}

// ---------------------------------------------------------------------------
// gamma^i / gamma^-i tables (double precision internally)
// ---------------------------------------------------------------------------
__global__ void gamma_kernel(const float* __restrict__ dec,
                             float* __restrict__ gp, float* __restrict__ gn)
{
    const int i = blockIdx.x, r = threadIdx.x;
    const double g  = 0.15 + 0.85 / (1.0 + exp(-(double)dec[r]));
    const double lg = log(g);
    gp[i * PR + r] = (float)exp((double)i * lg);
    gn[i * PR + r] = (float)exp(-(double)i * lg);
}

// ---------------------------------------------------------------------------
// concat(u, v) -> [D, 2R]
// ---------------------------------------------------------------------------
__global__ void concat_uv_kernel(const float* __restrict__ u, const float* __restrict__ v,
                                 float* __restrict__ uv)
{
    const int idx = blockIdx.x * blockDim.x + threadIdx.x;
    if (idx >= PD * PR) return;
    const int d = idx / PR, r = idx - d * PR;
    uv[(long long)d * 2 * PR + r]      = u[idx];
    uv[(long long)d * 2 * PR + PR + r] = v[idx];
}

// ---------------------------------------------------------------------------
// L2-normalize q/k rows and apply gamma^i / gamma^-i scaling.
// One warp per (b, i) row; lane handles r and r+32. k output transposed.
// ---------------------------------------------------------------------------
__global__ void qknorm_kernel(const float* __restrict__ qk,
                              const float* __restrict__ gp, const float* __restrict__ gn,
                              float* __restrict__ qt, float* __restrict__ ktT)
{
    const int row  = blockIdx.x * 8 + (threadIdx.x >> 5);   // 0 .. B*W-1
    const int lane = threadIdx.x & 31;
    const float* base = qk + (long long)row * (2 * PR);
    const float q0 = base[lane],          q1 = base[lane + 32];
    const float k0 = base[PR + lane],     k1 = base[PR + lane + 32];
    float sq = q0 * q0 + q1 * q1;
    float sk = k0 * k0 + k1 * k1;
#pragma unroll
    for (int o = 16; o; o >>= 1) {
        sq += __shfl_xor_sync(0xffffffffu, sq, o);
        sk += __shfl_xor_sync(0xffffffffu, sk, o);
    }
    const float iq = 1.f / fmaxf(sqrtf(sq), 1e-8f);
    const float ik = 1.f / fmaxf(sqrtf(sk), 1e-8f);
    const int b = row / PW, i = row - b * PW;
    const float* gpi = gp + (long long)i * PR;
    const float* gni = gn + (long long)i * PR;
    float* qrow = qt + (long long)row * PR;
    qrow[lane]      = q0 * iq * gpi[lane];
    qrow[lane + 32] = q1 * iq * gpi[lane + 32];
    float* kt = ktT + (long long)b * PR * PW;
    kt[(long long)lane * PW + i]        = k0 * ik * gni[lane];
    kt[(long long)(lane + 32) * PW + i] = k1 * ik * gni[lane + 32];
}

// ---------------------------------------------------------------------------
// Launcher
// ---------------------------------------------------------------------------
extern "C" void kernel_launch(void* const* d_in, const int* in_sizes, int n_in,
                              void* d_out, int out_size)
{
    (void)in_sizes; (void)out_size;
    if (n_in < 15) return;

    const float* h   = (const float*)d_in[0];
    const float* kb  = (const float*)d_in[1];
    const float* dec = (const float*)d_in[2];
    const float* gl  = (const float*)d_in[3];
    const float* al  = (const float*)d_in[4];
    const float* u   = (const float*)d_in[5];
    const float* v   = (const float*)d_in[6];
    const float* pw  = (const float*)d_in[7];
    const float* pb  = (const float*)d_in[8];
    const float* n1  = (const float*)d_in[9];
    const float* n2  = (const float*)d_in[10];
    const float* uw  = (const float*)d_in[11];
    const float* ub  = (const float*)d_in[12];
    const float* dw  = (const float*)d_in[13];
    const float* db  = (const float*)d_in[14];
    float* out = (float*)d_out;

    float *hn, *att, *Mb, *qkraw, *qt, *ktT, *uv, *gp, *gn, *gelu;
    cudaGetSymbolAddress((void**)&hn,    g_hnorm);
    cudaGetSymbolAddress((void**)&att,   g_attn);
    cudaGetSymbolAddress((void**)&Mb,    g_M);
    cudaGetSymbolAddress((void**)&qkraw, g_qkraw);
    cudaGetSymbolAddress((void**)&qt,    g_qt);
    cudaGetSymbolAddress((void**)&ktT,   g_ktT);
    cudaGetSymbolAddress((void**)&uv,    g_uv);
    cudaGetSymbolAddress((void**)&gp,    g_gp);
    cudaGetSymbolAddress((void**)&gn,    g_gn);
    cudaGetSymbolAddress((void**)&gelu,  g_gelu);

    const long long WW = (long long)PW * PW;
    const long long WD = (long long)PW * PD;
    const long long WR = (long long)PW * PR;

    // 1. h_norm = rmsnorm(h, norm1_scale)
    rmsnorm_kernel<<<PBW, 256>>>(h, n1, hn);

    // 2. tables + concat
    concat_uv_kernel<<<(PD * PR + 255) / 256, 256>>>(u, v, uv);
    gamma_kernel<<<PW, PR>>>(dec, gp, gn);

    // 3. qk = h_norm @ [u|v]   [B*W, 2R]
    sgemm<0, false><<<dim3(1, PBW / 128, 1), 256>>>(
        hn, uv, qkraw, PBW, 2 * PR, PD, 0, 0, 0,
        nullptr, nullptr, nullptr, nullptr, 0);

    // 4. l2norm + gamma scaling -> q~ [B*W,R], k~^T [B,R,W]
    qknorm_kernel<<<PBW / 8, 256>>>(qkraw, gp, gn, qt, ktT);

    // 5. M = causal( gate*kb + alpha * q~ @ k~^T )   per batch, lower-tri blocks only
    sgemm<1, false><<<dim3(PW / 128, PW / 128, PB), 256>>>(
        qt, ktT, Mb, PW, PW, PR, WR, WR, WW,
        nullptr, kb, gl, al, 2);

    // 6. attn = M @ h_norm   (K loop truncated per row tile)
    sgemm<0, false><<<dim3(PD / 128, PW / 128, PB), 256>>>(
        Mb, hn, att, PW, PD, PW, WW, WD, WD,
        nullptr, nullptr, nullptr, nullptr, 1);

    // 7. h1 = h + attn @ proj_w^T + proj_b   -> d_out
    sgemm<3, true><<<dim3(PD / 128, PBW / 128, 1), 256>>>(
        att, pw, out, PBW, PD, PD, 0, 0, 0,
        pb, h, nullptr, nullptr, 0);

    // 8. m0 = rmsnorm(h1, norm2_scale)  (reuse hn)
    rmsnorm_kernel<<<PBW, 256>>>(out, n2, hn);

    // 9. g = gelu(m0 @ up_w^T + up_b)
    sgemm<4, true><<<dim3(2 * PD / 128, PBW / 128, 1), 256>>>(
        hn, uw, gelu, PBW, 2 * PD, PD, 0, 0, 0,
        ub, nullptr, nullptr, nullptr, 0);

    // 10. d_out += g @ down_w^T + down_b
    sgemm<5, true><<<dim3(PD / 128, PBW / 128, 1), 256>>>(
        gelu, dw, out, PBW, PD, 2 * PD, 0, 0, 0,
        db, nullptr, nullptr, nullptr, 0);
}

// round 14
// speedup vs baseline: 1.0013x; 1.0013x over previous
#include <cuda_runtime.h>
#include <math.h>

// Problem constants (fixed by setup_inputs)
#define PB   8
#define PW   1024
#define PD   1024
#define PR   64
#define PBW  (PB * PW)            // 8192

// ---------------------------------------------------------------------------
// Scratch (__device__ globals; no allocations anywhere)
// ---------------------------------------------------------------------------
__device__ float g_hnorm[(size_t)PBW * PD];        // 32 MB  rmsnorm1 out, reused for rmsnorm2 out
__device__ float g_attn [(size_t)PBW * PD];        // 32 MB  attention mix output
__device__ float g_M    [(size_t)PB * PW * PW];    // 32 MB  per-batch mixing matrix (causal)
__device__ float g_qkraw[(size_t)PBW * 2 * PR];    //  4 MB  raw qk projection
__device__ float g_qt   [(size_t)PBW * PR];        //  2 MB  q * gamma^i          [B*W, R]
__device__ float g_ktT  [(size_t)PB * PR * PW];    //  2 MB  (k * gamma^-j)^T     [B, R, W]
__device__ float g_uv   [(size_t)PD * 2 * PR];     // .5 MB  concat(u, v)
__device__ float g_gp   [(size_t)PW * PR];         //        gamma^i table
__device__ float g_gn   [(size_t)PW * PR];         //        gamma^-i table
__device__ float g_gelu [(size_t)PBW * 2 * PD];    // 64 MB  MLP hidden

// ---------------------------------------------------------------------------
// Tiled SGEMM: C[M,N] = A[M,K] @ B, 128x128 block, 8x8 per-thread microtile.
// BT=false: B is [K,N] row-major.  BT=true: B is weight [N,K] row-major (B^T).
// EPI: 0 plain store | 1 causal mask + gate*kb + alpha*acc | 3 +bias+residual
//      4 +bias then exact GELU | 5 +=bias+acc into C
// tri: 1 -> truncate K loop at (by+1)*128 (A block-lower-triangular)
//      2 -> skip blocks strictly above the diagonal (scores)
// ---------------------------------------------------------------------------
template<int EPI, bool BT>
__global__ __launch_bounds__(256, 2)
void sgemm(const float* __restrict__ A, const float* __restrict__ B,
           float* __restrict__ C, int M, int N, int K,
           long long sA, long long sB, long long sC,
           const float* __restrict__ bias, const float* __restrict__ extra,
           const float* __restrict__ g0, const float* __restrict__ g1,
           int tri)
{
    const int bx = blockIdx.x, by = blockIdx.y, bz = blockIdx.z;
    if (tri == 2 && bx > by) return;

    A += (long long)bz * sA;
    B += (long long)bz * sB;
    C += (long long)bz * sC;

    const int tid     = threadIdx.x;
    const int rowBase = by * 128;
    const int colBase = bx * 128;

    __shared__ float As[8][132];
    __shared__ float Bs[8][132];

    int Keff = K;
    if (tri == 1) { int kl = (by + 1) * 128; if (kl < Keff) Keff = kl; }

    // A tile loader: 128 rows x 8 cols, 2 threads/row (float4 each)
    const int ar  = tid >> 1;
    const int ac4 = (tid & 1) * 4;
    const long long aoff = (long long)(rowBase + ar) * K + ac4;

    // B tile loader
    int br, bc4;
    long long boff;
    if (BT) { br = tid >> 1; bc4 = (tid & 1) * 4;
              boff = (long long)(colBase + br) * K + bc4; }
    else    { br = tid >> 5; bc4 = (tid & 31) * 4;
              boff = (long long)br * N + colBase + bc4; }

    const int mBase = (tid >> 4) * 8;
    const int nBase = (tid & 15) * 8;

    float acc[8][8];
#pragma unroll
    for (int i = 0; i < 8; i++)
#pragma unroll
        for (int j = 0; j < 8; j++) acc[i][j] = 0.f;

    float4 aReg = *(const float4*)(A + aoff);
    float4 bReg = *(const float4*)(B + boff);

    for (int k0 = 0; k0 < Keff; k0 += 8) {
        __syncthreads();
        As[ac4 + 0][ar] = aReg.x; As[ac4 + 1][ar] = aReg.y;
        As[ac4 + 2][ar] = aReg.z; As[ac4 + 3][ar] = aReg.w;
        if (BT) {
            Bs[bc4 + 0][br] = bReg.x; Bs[bc4 + 1][br] = bReg.y;
            Bs[bc4 + 2][br] = bReg.z; Bs[bc4 + 3][br] = bReg.w;
        } else {
            *(float4*)&Bs[br][bc4] = bReg;
        }
        __syncthreads();

        if (k0 + 8 < Keff) {                       // register prefetch
            aReg = *(const float4*)(A + aoff + (k0 + 8));
            if (BT) bReg = *(const float4*)(B + boff + (k0 + 8));
            else    bReg = *(const float4*)(B + boff + (long long)(k0 + 8) * N);
        }

#pragma unroll
        for (int kk = 0; kk < 8; kk++) {
            float a[8], b[8];
            *(float4*)&a[0] = *(const float4*)&As[kk][mBase];
            *(float4*)&a[4] = *(const float4*)&As[kk][mBase + 4];
            *(float4*)&b[0] = *(const float4*)&Bs[kk][nBase];
            *(float4*)&b[4] = *(const float4*)&Bs[kk][nBase + 4];
#pragma unroll
            for (int i = 0; i < 8; i++)
#pragma unroll
                for (int j = 0; j < 8; j++)
                    acc[i][j] = fmaf(a[i], b[j], acc[i][j]);
        }
    }

    float gate = 0.f, alpha = 0.f;
    if (EPI == 1) {
        gate  = 1.f / (1.f + expf(-g0[0]));
        alpha = 1.f / (1.f + expf(-g1[0]));
    }

#pragma unroll
    for (int i = 0; i < 8; i++) {
        const int m = rowBase + mBase + i;
        const long long crow = (long long)m * N + colBase + nBase;
        if (EPI == 0) {
            *(float4*)&C[crow]     = make_float4(acc[i][0], acc[i][1], acc[i][2], acc[i][3]);
            *(float4*)&C[crow + 4] = make_float4(acc[i][4], acc[i][5], acc[i][6], acc[i][7]);
        } else if (EPI == 1) {
#pragma unroll
            for (int j = 0; j < 8; j++) {
                const int jj = colBase + nBase + j;
                float vv = 0.f;
                if (jj <= m)
                    vv = gate * extra[(long long)m * N + jj] + alpha * acc[i][j];
                C[crow + j] = vv;
            }
        } else if (EPI == 3) {
#pragma unroll
            for (int j = 0; j < 8; j++)
                C[crow + j] = acc[i][j] + bias[colBase + nBase + j] + extra[crow + j];
        } else if (EPI == 4) {
#pragma unroll
            for (int j = 0; j < 8; j++) {
                const float x = acc[i][j] + bias[colBase + nBase + j];
                C[crow + j] = 0.5f * x * (1.f + erff(x * 0.70710678118654752f));
            }
        } else if (EPI == 5) {
#pragma unroll
            for (int j = 0; j < 8; j++)
                C[crow + j] += acc[i][j] + bias[colBase + nBase + j];
        }
    }
}

// ---------------------------------------------------------------------------
// RMSNorm: one block per row, D = 1024, 256 threads (one float4 each)
// ---------------------------------------------------------------------------
__global__ void rmsnorm_kernel(const float* __restrict__ x, const float* __restrict__ scale,
                               float* __restrict__ y)
{
    const long long row = blockIdx.x;
    const int t = threadIdx.x;
    const float4 v  = ((const float4*)(x + row * PD))[t];
    float s = v.x * v.x + v.y * v.y + v.z * v.z + v.w * v.w;
#pragma unroll
    for (int o = 16; o; o >>= 1) s += __shfl_xor_sync(0xffffffffu, s, o);
    __shared__ float ws[8];
    if ((t & 31) == 0) ws[t >> 5] = s;
    __syncthreads();
    const float tot = ws[0] + ws[1] + ws[2] + ws[3] + ws[4] + ws[5] + ws[6] + ws[7];
    const float r = rsqrtf(tot * (1.f / PD) + 1e-8f);
    const float4 sc = ((const float4*)scale)[t];
    ((float4*)(y + row * PD))[t] =
        make_float4(v.x * r * sc.x, v.y * r * sc.y, v.z * r * sc.z, v.w * r * sc.w);
}

// ---------------------------------------------------------------------------
// gamma^i / gamma^-i tables (double precision internally)
// ---------------------------------------------------------------------------
__global__ void gamma_kernel(const float* __restrict__ dec,
                             float* __restrict__ gp, float* __restrict__ gn)
{
    const int i = blockIdx.x, r = threadIdx.x;
    const double g  = 0.15 + 0.85 / (1.0 + exp(-(double)dec[r]));
    const double lg = log(g);
    gp[i * PR + r] = (float)exp((double)i * lg);
    gn[i * PR + r] = (float)exp(-(double)i * lg);
}

// ---------------------------------------------------------------------------
// concat(u, v) -> [D, 2R]
// ---------------------------------------------------------------------------
__global__ void concat_uv_kernel(const float* __restrict__ u, const float* __restrict__ v,
                                 float* __restrict__ uv)
{
    const int idx = blockIdx.x * blockDim.x + threadIdx.x;
    if (idx >= PD * PR) return;
    const int d = idx / PR, r = idx - d * PR;
    uv[(long long)d * 2 * PR + r]      = u[idx];
    uv[(long long)d * 2 * PR + PR + r] = v[idx];
}

// ---------------------------------------------------------------------------
// L2-normalize q/k rows and apply gamma^i / gamma^-i scaling.
// One warp per (b, i) row; lane handles r and r+32. k output transposed.
// ---------------------------------------------------------------------------
__global__ void qknorm_kernel(const float* __restrict__ qk,
                              const float* __restrict__ gp, const float* __restrict__ gn,
                              float* __restrict__ qt, float* __restrict__ ktT)
{
    const int row  = blockIdx.x * 8 + (threadIdx.x >> 5);   // 0 .. B*W-1
    const int lane = threadIdx.x & 31;
    const float* base = qk + (long long)row * (2 * PR);
    const float q0 = base[lane],          q1 = base[lane + 32];
    const float k0 = base[PR + lane],     k1 = base[PR + lane + 32];
    float sq = q0 * q0 + q1 * q1;
    float sk = k0 * k0 + k1 * k1;
#pragma unroll
    for (int o = 16; o; o >>= 1) {
        sq += __shfl_xor_sync(0xffffffffu, sq, o);
        sk += __shfl_xor_sync(0xffffffffu, sk, o);
    }
    const float iq = 1.f / fmaxf(sqrtf(sq), 1e-8f);
    const float ik = 1.f / fmaxf(sqrtf(sk), 1e-8f);
    const int b = row / PW, i = row - b * PW;
    const float* gpi = gp + (long long)i * PR;
    const float* gni = gn + (long long)i * PR;
    float* qrow = qt + (long long)row * PR;
    qrow[lane]      = q0 * iq * gpi[lane];
    qrow[lane + 32] = q1 * iq * gpi[lane + 32];
    float* kt = ktT + (long long)b * PR * PW;
    kt[(long long)lane * PW + i]        = k0 * ik * gni[lane];
    kt[(long long)(lane + 32) * PW + i] = k1 * ik * gni[lane + 32];
}

// ---------------------------------------------------------------------------
// Launcher
// ---------------------------------------------------------------------------
extern "C" void kernel_launch(void* const* d_in, const int* in_sizes, int n_in,
                              void* d_out, int out_size)
{
    (void)in_sizes; (void)out_size;
    if (n_in < 15) return;

    const float* h   = (const float*)d_in[0];
    const float* kb  = (const float*)d_in[1];
    const float* dec = (const float*)d_in[2];
    const float* gl  = (const float*)d_in[3];
    const float* al  = (const float*)d_in[4];
    const float* u   = (const float*)d_in[5];
    const float* v   = (const float*)d_in[6];
    const float* pw  = (const float*)d_in[7];
    const float* pb  = (const float*)d_in[8];
    const float* n1  = (const float*)d_in[9];
    const float* n2  = (const float*)d_in[10];
    const float* uw  = (const float*)d_in[11];
    const float* ub  = (const float*)d_in[12];
    const float* dw  = (const float*)d_in[13];
    const float* db  = (const float*)d_in[14];
    float* out = (float*)d_out;

    float *hn, *att, *Mb, *qkraw, *qt, *ktT, *uv, *gp, *gn, *gelu;
    cudaGetSymbolAddress((void**)&hn,    g_hnorm);
    cudaGetSymbolAddress((void**)&att,   g_attn);
    cudaGetSymbolAddress((void**)&Mb,    g_M);
    cudaGetSymbolAddress((void**)&qkraw, g_qkraw);
    cudaGetSymbolAddress((void**)&qt,    g_qt);
    cudaGetSymbolAddress((void**)&ktT,   g_ktT);
    cudaGetSymbolAddress((void**)&uv,    g_uv);
    cudaGetSymbolAddress((void**)&gp,    g_gp);
    cudaGetSymbolAddress((void**)&gn,    g_gn);
    cudaGetSymbolAddress((void**)&gelu,  g_gelu);

    const long long WW = (long long)PW * PW;
    const long long WD = (long long)PW * PD;
    const long long WR = (long long)PW * PR;

    // 1. h_norm = rmsnorm(h, norm1_scale)
    rmsnorm_kernel<<<PBW, 256>>>(h, n1, hn);

    // 2. tables + concat
    concat_uv_kernel<<<(PD * PR + 255) / 256, 256>>>(u, v, uv);
    gamma_kernel<<<PW, PR>>>(dec, gp, gn);

    // 3. qk = h_norm @ [u|v]   [B*W, 2R]
    sgemm<0, false><<<dim3(1, PBW / 128, 1), 256>>>(
        hn, uv, qkraw, PBW, 2 * PR, PD, 0, 0, 0,
        nullptr, nullptr, nullptr, nullptr, 0);

    // 4. l2norm + gamma scaling -> q~ [B*W,R], k~^T [B,R,W]
    qknorm_kernel<<<PBW / 8, 256>>>(qkraw, gp, gn, qt, ktT);

    // 5. M = causal( gate*kb + alpha * q~ @ k~^T )   per batch, lower-tri blocks only
    sgemm<1, false><<<dim3(PW / 128, PW / 128, PB), 256>>>(
        qt, ktT, Mb, PW, PW, PR, WR, WR, WW,
        nullptr, kb, gl, al, 2);

    // 6. attn = M @ h_norm   (K loop truncated per row tile)
    sgemm<0, false><<<dim3(PD / 128, PW / 128, PB), 256>>>(
        Mb, hn, att, PW, PD, PW, WW, WD, WD,
        nullptr, nullptr, nullptr, nullptr, 1);

    // 7. h1 = h + attn @ proj_w^T + proj_b   -> d_out
    sgemm<3, true><<<dim3(PD / 128, PBW / 128, 1), 256>>>(
        att, pw, out, PBW, PD, PD, 0, 0, 0,
        pb, h, nullptr, nullptr, 0);

    // 8. m0 = rmsnorm(h1, norm2_scale)  (reuse hn)
    rmsnorm_kernel<<<PBW, 256>>>(out, n2, hn);

    // 9. g = gelu(m0 @ up_w^T + up_b)
    sgemm<4, true><<<dim3(2 * PD / 128, PBW / 128, 1), 256>>>(
        hn, uw, gelu, PBW, 2 * PD, PD, 0, 0, 0,
        ub, nullptr, nullptr, nullptr, 0);

    // 10. d_out += g @ down_w^T + down_b
    sgemm<5, true><<<dim3(PD / 128, PBW / 128, 1), 256>>>(
        gelu, dw, out, PBW, PD, 2 * PD, 0, 0, 0,
        db, nullptr, nullptr, nullptr, 0);
}